// round 1
// baseline (speedup 1.0000x reference)
#include <cuda_runtime.h>

#define NB 4
#define NC 128
#define NH 192
#define NW 192
#define ND 21          // displacements per axis
#define ND2 441
#define HR 158         // raw correlation grid
#define WR 158
#define WRP 160        // padded raw row stride (float4-aligned stores)
#define HO 156
#define WO 156
#define CCH 4          // channel chunk

// Scratch: raw correlation volume [B][441][158][160] = ~178 MB (static device mem, allowed)
__device__ __align__(16) float g_raw[(size_t)NB * ND2 * HR * WRP];

// Pass 1: raw[b, dyi*21+dxi, y, x] = sum_c A[c, y+17, x+17] * Bpad[c, y+17+dy, x+17+dx]
// Block: 160 threads = 8 rows x 20 x-groups (8 consecutive x each).
// Grid: (ytile=20, dyi=21, b*2 + dx-half). Each block computes 11 dx values.
__global__ __launch_bounds__(160, 2)
void corr_pass1(const float* __restrict__ A, const float* __restrict__ B) {
    const int yt  = blockIdx.x;            // 0..19  (8 rows each)
    const int dyi = blockIdx.y;            // 0..20
    const int bz  = blockIdx.z;            // 0..7
    const int b   = bz >> 1;
    const int d0  = (bz & 1) * 10;         // dxi base: 0 or 10 (11 each; dxi=10 duplicated, identical value)
    const int d   = 2 * dyi - 20;          // dy displacement

    const int tid = threadIdx.x;
    const int r   = tid / 20;              // row in tile 0..7
    const int g   = tid % 20;              // x-group
    const int x0  = g * 8;                 // covers x0..x0+7 (guarded by padded raw buffer)

    const int y = yt * 8 + r;              // raw row owned by this thread

    // row strides 164/180 are ==4 (mod 8): even/odd rows use disjoint bank halves
    __shared__ __align__(16) float sA[CCH][8][164];
    __shared__ __align__(16) float sB[CCH][8][180];

    float acc[11][8];
    #pragma unroll
    for (int j = 0; j < 11; ++j)
        #pragma unroll
        for (int o = 0; o < 8; ++o) acc[j][o] = 0.f;

    const float* Ab = A + (size_t)b * NC * NH * NW;
    const float* Bb = B + (size_t)b * NC * NH * NW;

    for (int c0 = 0; c0 < NC; c0 += CCH) {
        // ---- load A tile: rows y+17, cols 17..174 (never touches padding) ----
        for (int idx = tid; idx < CCH * 8 * 164; idx += 160) {
            int cc  = idx / (8 * 164);
            int rem = idx % (8 * 164);
            int rr  = rem / 164;
            int col = rem % 164;
            int gy  = yt * 8 + rr;
            float v = 0.f;
            if (col < 158 && gy < HR)
                v = Ab[((size_t)(c0 + cc) * NH + (gy + 17)) * NW + (col + 17)];
            sA[cc][rr][col] = v;
        }
        // ---- load B tile: sB[..][k] = Bpad[row = y+17+d, col = k + 2*d0 - 3], zero OOB ----
        for (int idx = tid; idx < CCH * 8 * 180; idx += 160) {
            int cc  = idx / (8 * 180);
            int rem = idx % (8 * 180);
            int rr  = rem / 180;
            int k   = rem % 180;
            int gy  = yt * 8 + rr;
            int grow = gy + 17 + d;
            int gcol = k + 2 * d0 - 3;
            float v = 0.f;
            if (gy < HR && grow >= 0 && grow < NH && gcol >= 0 && gcol < NW)
                v = Bb[((size_t)(c0 + cc) * NH + grow) * NW + gcol];
            sB[cc][rr][k] = v;
        }
        __syncthreads();

        #pragma unroll
        for (int cc = 0; cc < CCH; ++cc) {
            float a[8], bb[28];
            #pragma unroll
            for (int m = 0; m < 2; ++m) {
                float4 t = *reinterpret_cast<const float4*>(&sA[cc][r][x0 + 4 * m]);
                a[4*m+0] = t.x; a[4*m+1] = t.y; a[4*m+2] = t.z; a[4*m+3] = t.w;
            }
            #pragma unroll
            for (int m = 0; m < 7; ++m) {
                float4 t = *reinterpret_cast<const float4*>(&sB[cc][r][x0 + 4 * m]);
                bb[4*m+0] = t.x; bb[4*m+1] = t.y; bb[4*m+2] = t.z; bb[4*m+3] = t.w;
            }
            // acc[j][o]: output x = x0+o, dxi = d0+j; B operand index = 2j+o (<=27)
            #pragma unroll
            for (int j = 0; j < 11; ++j)
                #pragma unroll
                for (int o = 0; o < 8; ++o)
                    acc[j][o] += a[o] * bb[2 * j + o];
        }
        __syncthreads();
    }

    if (y < HR) {
        #pragma unroll
        for (int j = 0; j < 11; ++j) {
            int ch = dyi * ND + (d0 + j);
            size_t base = (((size_t)b * ND2 + ch) * HR + y) * WRP + x0;
            *reinterpret_cast<float4*>(&g_raw[base]) =
                make_float4(acc[j][0], acc[j][1], acc[j][2], acc[j][3]);
            *reinterpret_cast<float4*>(&g_raw[base + 4]) =
                make_float4(acc[j][4], acc[j][5], acc[j][6], acc[j][7]);
        }
    }
}

// Pass 2: 3x3 box sum / 1152. Each thread: fixed col j, 4 consecutive output rows.
__global__ void corr_pass2(float* __restrict__ out) {
    const int j  = threadIdx.x;                         // 0..155
    const int q  = blockIdx.y * blockDim.y + threadIdx.y;
    const int ch = blockIdx.z;                          // b*441 + d
    if (q >= 39) return;
    const int i0 = q * 4;
    const float inv = 1.0f / 1152.0f;

    const float* rawb = g_raw + (size_t)ch * HR * WRP;
    float s[6];
    #pragma unroll
    for (int rr = 0; rr < 6; ++rr) {
        const float* row = rawb + (size_t)(i0 + rr) * WRP + j;
        s[rr] = row[0] + row[1] + row[2];
    }
    float* ob = out + (size_t)ch * HO * WO + j;
    ob[(size_t)(i0 + 0) * WO] = (s[0] + s[1] + s[2]) * inv;
    ob[(size_t)(i0 + 1) * WO] = (s[1] + s[2] + s[3]) * inv;
    ob[(size_t)(i0 + 2) * WO] = (s[2] + s[3] + s[4]) * inv;
    ob[(size_t)(i0 + 3) * WO] = (s[3] + s[4] + s[5]) * inv;
}

extern "C" void kernel_launch(void* const* d_in, const int* in_sizes, int n_in,
                              void* d_out, int out_size) {
    const float* in1 = (const float*)d_in[0];
    const float* in2 = (const float*)d_in[1];
    float* out = (float*)d_out;

    dim3 g1(20, 21, 8), b1(160);
    corr_pass1<<<g1, b1>>>(in1, in2);

    dim3 g2(1, 10, NB * ND2), b2(156, 4);
    corr_pass2<<<g2, b2>>>(out);
}

// round 2
// speedup vs baseline: 2.3828x; 2.3828x over previous
#include <cuda_runtime.h>

#define NB 4
#define NC 128
#define NH 192
#define NW 192
#define ND 21
#define ND2 441
#define HR 158
#define WRP 160        // padded raw row stride
#define HO 156
#define WO 156
#define CCH 4

#define APAD_H 160
#define APAD_W 160     // 40 quads
#define BPAD_H 200
#define BPAD_W 204     // 51 quads
#define SA_STRIDE 164  // 41 quads (odd -> conflict-free with r*41+q)
#define SB_STRIDE 188  // 47 quads (odd)

__device__ __align__(16) float g_Apad[(size_t)NB * NC * APAD_H * APAD_W];  // ~52 MB
__device__ __align__(16) float g_Bpad[(size_t)NB * NC * BPAD_H * BPAD_W];  // ~84 MB
__device__ __align__(16) float g_raw [(size_t)NB * ND2 * HR * WRP];        // ~178 MB

// ---------------- Pass 0: pad inputs ----------------
// Apad[b][c][y][k] = in1[b][c][y+17][k+17]  (always in range: y<160 -> y+17<=176)
__global__ void pad_A(const float* __restrict__ in1) {
    long idx = (long)blockIdx.x * blockDim.x + threadIdx.x;
    if (idx >= (long)NB * NC * APAD_H * APAD_W) return;
    int k = (int)(idx % APAD_W);
    long rest = idx / APAD_W;
    int y = (int)(rest % APAD_H);
    long bc = rest / APAD_H;
    g_Apad[idx] = in1[(bc * NH + y + 17) * NW + (k + 17)];
}

// Bpad[b][c][yy][xx] = in2[b][c][yy-3][xx-3] if in range else 0
__global__ void pad_B(const float* __restrict__ in2) {
    long idx = (long)blockIdx.x * blockDim.x + threadIdx.x;
    if (idx >= (long)NB * NC * BPAD_H * BPAD_W) return;
    int xx = (int)(idx % BPAD_W);
    long rest = idx / BPAD_W;
    int yy = (int)(rest % BPAD_H);
    long bc = rest / BPAD_H;
    int sy = yy - 3, sx = xx - 3;
    float v = 0.f;
    if ((unsigned)sy < NH && (unsigned)sx < NW)
        v = in2[(bc * NH + sy) * NW + sx];
    g_Bpad[idx] = v;
}

// ---------------- Pass 1: raw correlation ----------------
// raw[b, dyi*21+dxi, y, x] = sum_c Apad[c,y,x] * Bpad[c, y+20+d, x+2*dxi]
// block: 160 thr = 8 rows (r=tid&7) x 20 x-groups (g=tid>>3, 8 x each)
// grid: (ytile 20, dyi 21, b*2 + dx-half); 11 dx per block (dxi=10 duplicated, identical)
__global__ __launch_bounds__(160, 2)
void corr_pass1() {
    const int yt  = blockIdx.x;
    const int dyi = blockIdx.y;
    const int bz  = blockIdx.z;
    const int b   = bz >> 1;
    const int d0  = (bz & 1) * 10;
    const int d   = 2 * dyi - 20;

    const int tid = threadIdx.x;
    const int r   = tid & 7;
    const int g   = tid >> 3;
    const int x0  = g * 8;
    const int y   = yt * 8 + r;

    __shared__ __align__(16) float sA[CCH][8][SA_STRIDE];
    __shared__ __align__(16) float sB[CCH][8][SB_STRIDE];

    float acc[11][8];
    #pragma unroll
    for (int j = 0; j < 11; ++j)
        #pragma unroll
        for (int o = 0; o < 8; ++o) acc[j][o] = 0.f;

    const float4* Aq = (const float4*)g_Apad;
    const float4* Bq = (const float4*)g_Bpad;
    // A quad index for (c, rr, q): ((b*NC + c)*APAD_H + yt*8 + rr)*40 + q
    const long abase = ((long)b * NC * APAD_H + yt * 8) * 40;
    // B quad index: ((b*NC + c)*BPAD_H + yt*8 + 20 + d + rr)*51 + q + (d0>>1)
    const long bbase = ((long)b * NC * BPAD_H + yt * 8 + 20 + d) * 51 + (d0 >> 1);

    const int aq = tid % 40, ar = tid / 40;   // A: 320 quads, 2 per thread

    for (int c0 = 0; c0 < NC; c0 += CCH) {
        #pragma unroll
        for (int cc = 0; cc < CCH; ++cc) {
            const int c = c0 + cc;
            // ---- A tile: 8 rows x 40 quads ----
            {
                long rowq = abase + (long)c * (APAD_H * 40);
                float4 v0 = Aq[rowq + (long)ar * 40 + aq];
                float4 v1 = Aq[rowq + (long)(ar + 4) * 40 + aq];
                *reinterpret_cast<float4*>(&sA[cc][ar][aq * 4])     = v0;
                *reinterpret_cast<float4*>(&sA[cc][ar + 4][aq * 4]) = v1;
            }
            // ---- B tile: 8 rows x 46 quads = 368 quads ----
            {
                long rowq = bbase + (long)c * (BPAD_H * 51);
                #pragma unroll
                for (int it = 0; it < 3; ++it) {
                    int idx = tid + it * 160;
                    if (idx < 368) {
                        int br = idx / 46, bqi = idx % 46;
                        float4 v = Bq[rowq + (long)br * 51 + bqi];
                        *reinterpret_cast<float4*>(&sB[cc][br][bqi * 4]) = v;
                    }
                }
            }
        }
        __syncthreads();

        #pragma unroll
        for (int cc = 0; cc < CCH; ++cc) {
            float a[8], bb[28];
            #pragma unroll
            for (int m = 0; m < 2; ++m) {
                float4 t = *reinterpret_cast<const float4*>(&sA[cc][r][x0 + 4 * m]);
                a[4*m+0] = t.x; a[4*m+1] = t.y; a[4*m+2] = t.z; a[4*m+3] = t.w;
            }
            #pragma unroll
            for (int m = 0; m < 7; ++m) {
                float4 t = *reinterpret_cast<const float4*>(&sB[cc][r][x0 + 4 * m]);
                bb[4*m+0] = t.x; bb[4*m+1] = t.y; bb[4*m+2] = t.z; bb[4*m+3] = t.w;
            }
            #pragma unroll
            for (int j = 0; j < 11; ++j)
                #pragma unroll
                for (int o = 0; o < 8; ++o)
                    acc[j][o] += a[o] * bb[2 * j + o];
        }
        __syncthreads();
    }

    if (y < HR) {
        #pragma unroll
        for (int j = 0; j < 11; ++j) {
            int ch = dyi * ND + (d0 + j);
            size_t base = (((size_t)b * ND2 + ch) * HR + y) * WRP + x0;
            *reinterpret_cast<float4*>(&g_raw[base]) =
                make_float4(acc[j][0], acc[j][1], acc[j][2], acc[j][3]);
            *reinterpret_cast<float4*>(&g_raw[base + 4]) =
                make_float4(acc[j][4], acc[j][5], acc[j][6], acc[j][7]);
        }
    }
}

// ---------------- Pass 2: 3x3 box sum / 1152 ----------------
__global__ void corr_pass2(float* __restrict__ out) {
    const int j  = threadIdx.x;
    const int q  = blockIdx.y * blockDim.y + threadIdx.y;
    const int ch = blockIdx.z;
    if (q >= 39) return;
    const int i0 = q * 4;
    const float inv = 1.0f / 1152.0f;

    const float* rawb = g_raw + (size_t)ch * HR * WRP;
    float s[6];
    #pragma unroll
    for (int rr = 0; rr < 6; ++rr) {
        const float* row = rawb + (size_t)(i0 + rr) * WRP + j;
        s[rr] = row[0] + row[1] + row[2];
    }
    float* ob = out + (size_t)ch * HO * WO + j;
    ob[(size_t)(i0 + 0) * WO] = (s[0] + s[1] + s[2]) * inv;
    ob[(size_t)(i0 + 1) * WO] = (s[1] + s[2] + s[3]) * inv;
    ob[(size_t)(i0 + 2) * WO] = (s[2] + s[3] + s[4]) * inv;
    ob[(size_t)(i0 + 3) * WO] = (s[3] + s[4] + s[5]) * inv;
}

extern "C" void kernel_launch(void* const* d_in, const int* in_sizes, int n_in,
                              void* d_out, int out_size) {
    const float* in1 = (const float*)d_in[0];
    const float* in2 = (const float*)d_in[1];
    float* out = (float*)d_out;

    {
        long nA = (long)NB * NC * APAD_H * APAD_W;
        pad_A<<<(unsigned)((nA + 255) / 256), 256>>>(in1);
        long nBp = (long)NB * NC * BPAD_H * BPAD_W;
        pad_B<<<(unsigned)((nBp + 255) / 256), 256>>>(in2);
    }

    dim3 g1(20, 21, 8), b1(160);
    corr_pass1<<<g1, b1>>>();

    dim3 g2(1, 10, NB * ND2), b2(156, 4);
    corr_pass2<<<g2, b2>>>(out);
}

// round 3
// speedup vs baseline: 2.5438x; 1.0676x over previous
#include <cuda_runtime.h>
#include <cstdint>

#define NB 4
#define NC 128
#define NH 192
#define NW 192
#define ND 21
#define ND2 441
#define HR 158
#define WRP 160
#define HO 156
#define WO 156

#define APAD_H 160
#define APAD_W 160
#define BPAD_H 200
#define BPAD_W 204

// smem layout (bytes)
#define A_ROW 656           // 164 floats (41 quads, odd -> conflict-free)
#define A_CC  (8 * A_ROW)   // 5248
#define A_STAGE (4 * A_CC)  // 20992
#define B_ROW 752           // 188 floats (47 quads, odd)
#define B_CC  (8 * B_ROW)   // 6016
#define B_STAGE (4 * B_CC)  // 24064
#define A_OFF 128
#define B_OFF (A_OFF + 2 * A_STAGE)        // 42112
#define SMEM_BYTES (B_OFF + 2 * B_STAGE)   // 90240
#define STAGE_TX (32 * 640 + 32 * 736)     // 44032

__device__ __align__(16) float g_Apad[(size_t)NB * NC * APAD_H * APAD_W];
__device__ __align__(16) float g_Bpad[(size_t)NB * NC * BPAD_H * BPAD_W];
__device__ __align__(16) float g_raw [(size_t)NB * ND2 * HR * WRP];

// ---------------- Pass 0: pad inputs ----------------
__global__ void pad_A(const float* __restrict__ in1) {
    long idx = (long)blockIdx.x * blockDim.x + threadIdx.x;
    if (idx >= (long)NB * NC * APAD_H * APAD_W) return;
    int k = (int)(idx % APAD_W);
    long rest = idx / APAD_W;
    int y = (int)(rest % APAD_H);
    long bc = rest / APAD_H;
    g_Apad[idx] = in1[(bc * NH + y + 17) * NW + (k + 17)];
}

__global__ void pad_B(const float* __restrict__ in2) {
    long idx = (long)blockIdx.x * blockDim.x + threadIdx.x;
    if (idx >= (long)NB * NC * BPAD_H * BPAD_W) return;
    int xx = (int)(idx % BPAD_W);
    long rest = idx / BPAD_W;
    int yy = (int)(rest % BPAD_H);
    long bc = rest / BPAD_H;
    int sy = yy - 3, sx = xx - 3;
    float v = 0.f;
    if ((unsigned)sy < NH && (unsigned)sx < NW)
        v = in2[(bc * NH + sy) * NW + sx];
    g_Bpad[idx] = v;
}

// ---------------- TMA / mbarrier helpers ----------------
__device__ __forceinline__ void bulk_cp(uint32_t dst, const void* src,
                                        uint32_t bytes, uint32_t mbar) {
    asm volatile(
        "cp.async.bulk.shared::cta.global.mbarrier::complete_tx::bytes [%0], [%1], %2, [%3];"
        :: "r"(dst), "l"(src), "r"(bytes), "r"(mbar) : "memory");
}

__device__ __forceinline__ void mbar_wait(uint32_t mbar, uint32_t parity) {
    asm volatile(
        "{\n\t.reg .pred P;\n\t"
        "W_%=:\n\t"
        "mbarrier.try_wait.parity.acquire.cta.shared::cta.b64 P, [%0], %1, 10000000;\n\t"
        "@P bra D_%=;\n\t"
        "bra W_%=;\n\t"
        "D_%=:\n\t}"
        :: "r"(mbar), "r"(parity) : "memory");
}

__device__ __forceinline__ void fill_stage(uint32_t sbase, int i, int lane,
                                           int b, int yt, int d, int d0) {
    const int s = i & 1;
    const uint32_t mbar = sbase + s * 8;
    if (lane == 0)
        asm volatile("mbarrier.arrive.expect_tx.shared.b64 _, [%0], %1;"
                     :: "r"(mbar), "r"((uint32_t)STAGE_TX) : "memory");
    __syncwarp();
    const int ccl = lane >> 3, rrl = lane & 7;
    const int c = i * 4 + ccl;
    const char* srcA = (const char*)g_Apad +
        ((long)(b * NC + c) * APAD_H + yt * 8 + rrl) * (long)(APAD_W * 4);
    const char* srcB = (const char*)g_Bpad +
        ((long)(b * NC + c) * BPAD_H + yt * 8 + 20 + d + rrl) * (long)(BPAD_W * 4)
        + (d0 >> 1) * 16;
    bulk_cp(sbase + A_OFF + s * A_STAGE + ccl * A_CC + rrl * A_ROW, srcA, 640, mbar);
    bulk_cp(sbase + B_OFF + s * B_STAGE + ccl * B_CC + rrl * B_ROW, srcB, 736, mbar);
}

// ---------------- Pass 1: raw correlation ----------------
// grid (dyi*2+half, yt, b); block 160 = 8 rows x 20 x-groups (8 x each), 11 dx.
extern __shared__ char smem_dyn[];

__global__ __launch_bounds__(160, 2)
void corr_pass1() {
    const int bx  = blockIdx.x;
    const int dyi = bx >> 1;
    const int d0  = (bx & 1) * 10;
    const int yt  = blockIdx.y;
    const int b   = blockIdx.z;
    const int d   = 2 * dyi - 20;

    const int tid = threadIdx.x;
    const int r   = tid & 7;
    const int g   = tid >> 3;
    const int x0  = g * 8;
    const int y   = yt * 8 + r;

    char* smc = smem_dyn;
    const uint32_t sbase = (uint32_t)__cvta_generic_to_shared(smc);

    if (tid == 0) {
        asm volatile("mbarrier.init.shared.b64 [%0], 1;" :: "r"(sbase + 0) : "memory");
        asm volatile("mbarrier.init.shared.b64 [%0], 1;" :: "r"(sbase + 8) : "memory");
        asm volatile("fence.proxy.async.shared::cta;" ::: "memory");
    }
    __syncthreads();

    if (tid < 32) {
        fill_stage(sbase, 0, tid, b, yt, d, d0);
        fill_stage(sbase, 1, tid, b, yt, d, d0);
    }

    float acc[11][8];
    #pragma unroll
    for (int j = 0; j < 11; ++j)
        #pragma unroll
        for (int o = 0; o < 8; ++o) acc[j][o] = 0.f;

    for (int i = 0; i < 32; ++i) {
        const int s = i & 1;
        mbar_wait(sbase + s * 8, (i >> 1) & 1);

        #pragma unroll
        for (int cc = 0; cc < 4; ++cc) {
            const float4* aq = (const float4*)(smc + A_OFF + s * A_STAGE +
                                               cc * A_CC + r * A_ROW + x0 * 4);
            const float4* bq = (const float4*)(smc + B_OFF + s * B_STAGE +
                                               cc * B_CC + r * B_ROW + x0 * 4);
            float a[8], bb[28];
            #pragma unroll
            for (int m = 0; m < 2; ++m) {
                float4 t = aq[m];
                a[4*m+0] = t.x; a[4*m+1] = t.y; a[4*m+2] = t.z; a[4*m+3] = t.w;
            }
            #pragma unroll
            for (int m = 0; m < 7; ++m) {
                float4 t = bq[m];
                bb[4*m+0] = t.x; bb[4*m+1] = t.y; bb[4*m+2] = t.z; bb[4*m+3] = t.w;
            }
            #pragma unroll
            for (int j = 0; j < 11; ++j)
                #pragma unroll
                for (int o = 0; o < 8; ++o)
                    acc[j][o] += a[o] * bb[2 * j + o];
        }
        __syncthreads();
        if (tid < 32 && i + 2 < 32)
            fill_stage(sbase, i + 2, tid, b, yt, d, d0);
    }

    if (y < HR) {
        #pragma unroll
        for (int j = 0; j < 11; ++j) {
            int ch = dyi * ND + (d0 + j);
            size_t base = (((size_t)b * ND2 + ch) * HR + y) * WRP + x0;
            *reinterpret_cast<float4*>(&g_raw[base]) =
                make_float4(acc[j][0], acc[j][1], acc[j][2], acc[j][3]);
            *reinterpret_cast<float4*>(&g_raw[base + 4]) =
                make_float4(acc[j][4], acc[j][5], acc[j][6], acc[j][7]);
        }
    }
}

// ---------------- Pass 2: 3x3 box sum / 1152 ----------------
__global__ void corr_pass2(float* __restrict__ out) {
    const int j  = threadIdx.x;
    const int q  = blockIdx.y * blockDim.y + threadIdx.y;
    const int ch = blockIdx.z;
    if (q >= 39) return;
    const int i0 = q * 4;
    const float inv = 1.0f / 1152.0f;

    const float* rawb = g_raw + (size_t)ch * HR * WRP;
    float s[6];
    #pragma unroll
    for (int rr = 0; rr < 6; ++rr) {
        const float* row = rawb + (size_t)(i0 + rr) * WRP + j;
        s[rr] = row[0] + row[1] + row[2];
    }
    float* ob = out + (size_t)ch * HO * WO + j;
    ob[(size_t)(i0 + 0) * WO] = (s[0] + s[1] + s[2]) * inv;
    ob[(size_t)(i0 + 1) * WO] = (s[1] + s[2] + s[3]) * inv;
    ob[(size_t)(i0 + 2) * WO] = (s[2] + s[3] + s[4]) * inv;
    ob[(size_t)(i0 + 3) * WO] = (s[3] + s[4] + s[5]) * inv;
}

extern "C" void kernel_launch(void* const* d_in, const int* in_sizes, int n_in,
                              void* d_out, int out_size) {
    const float* in1 = (const float*)d_in[0];
    const float* in2 = (const float*)d_in[1];
    float* out = (float*)d_out;

    {
        long nA = (long)NB * NC * APAD_H * APAD_W;
        pad_A<<<(unsigned)((nA + 255) / 256), 256>>>(in1);
        long nBp = (long)NB * NC * BPAD_H * BPAD_W;
        pad_B<<<(unsigned)((nBp + 255) / 256), 256>>>(in2);
    }

    cudaFuncSetAttribute(corr_pass1,
                         cudaFuncAttributeMaxDynamicSharedMemorySize, SMEM_BYTES);

    dim3 g1(42, 20, 4), b1(160);
    corr_pass1<<<g1, b1, SMEM_BYTES>>>();

    dim3 g2(1, 10, NB * ND2), b2(156, 4);
    corr_pass2<<<g2, b2>>>(out);
}

// round 4
// speedup vs baseline: 5.3015x; 2.0841x over previous
#include <cuda_runtime.h>
#include <cstdint>

#define NB 4
#define NC 128
#define NH 192
#define NW 192
#define ND 21
#define ND2 441
#define HR 158
#define WRP 160
#define HO 156
#define WO 156

#define APAD_W 164     // floats per A row (41 quads, odd)
#define BPAD_H 200
#define BPAD_W 212     // floats per B row (53 quads, odd)

// smem layout (bytes)
#define A_ROW 656            // 164 floats
#define A_CC  (8 * A_ROW)    // 5248
#define A_STAGE (4 * A_CC)   // 20992
#define B_ROW 848            // 212 floats
#define B_CC  (8 * B_ROW)    // 6784
#define B_STAGE (4 * B_CC)   // 27136
#define A_OFF 128
#define B_OFF (A_OFF + 2 * A_STAGE)        // 42112
#define SMEM_BYTES (B_OFF + 2 * B_STAGE)   // 96384
#define STAGE_TX (A_STAGE + B_STAGE)       // 48128

// A tile-major: [b][yt][c][rr 8][164]   (~54 MB)
__device__ __align__(16) float g_Apad[(size_t)NB * 20 * NC * 8 * APAD_W];
// B: [b][c][200][212]                    (~87 MB)
__device__ __align__(16) float g_Bpad[(size_t)NB * NC * BPAD_H * BPAD_W];
__device__ __align__(16) float g_raw [(size_t)NB * ND2 * HR * WRP];

// ---------------- Pass 0: pad/reshape inputs ----------------
__global__ void pad_A(const float* __restrict__ in1) {
    long idx = (long)blockIdx.x * blockDim.x + threadIdx.x;
    if (idx >= (long)NB * 20 * NC * 8 * APAD_W) return;
    int col = (int)(idx % APAD_W);
    long rest = idx / APAD_W;
    int rr = (int)(rest % 8);
    rest /= 8;
    int c = (int)(rest % NC);
    rest /= NC;
    int yt = (int)(rest % 20);
    int b  = (int)(rest / 20);
    // always in range: col+17 <= 180, yt*8+rr+17 <= 176
    g_Apad[idx] = in1[(((long)b * NC + c) * NH + yt * 8 + rr + 17) * NW + (col + 17)];
}

__global__ void pad_B(const float* __restrict__ in2) {
    long idx = (long)blockIdx.x * blockDim.x + threadIdx.x;
    if (idx >= (long)NB * NC * BPAD_H * BPAD_W) return;
    int xx = (int)(idx % BPAD_W);
    long rest = idx / BPAD_W;
    int yy = (int)(rest % BPAD_H);
    long bc = rest / BPAD_H;
    int sy = yy - 3, sx = xx - 3;
    float v = 0.f;
    if ((unsigned)sy < NH && (unsigned)sx < NW)
        v = in2[(bc * NH + sy) * NW + sx];
    g_Bpad[idx] = v;
}

// ---------------- TMA / mbarrier helpers ----------------
__device__ __forceinline__ void bulk_cp(uint32_t dst, const void* src,
                                        uint32_t bytes, uint32_t mbar) {
    asm volatile(
        "cp.async.bulk.shared::cta.global.mbarrier::complete_tx::bytes [%0], [%1], %2, [%3];"
        :: "r"(dst), "l"(src), "r"(bytes), "r"(mbar) : "memory");
}

__device__ __forceinline__ void mbar_wait(uint32_t mbar, uint32_t parity) {
    asm volatile(
        "{\n\t.reg .pred P;\n\t"
        "W_%=:\n\t"
        "mbarrier.try_wait.parity.acquire.cta.shared::cta.b64 P, [%0], %1, 10000000;\n\t"
        "@P bra D_%=;\n\t"
        "bra W_%=;\n\t"
        "D_%=:\n\t}"
        :: "r"(mbar), "r"(parity) : "memory");
}

// One stage = 1 big A copy + 4 per-channel B copies, issued by a single thread.
__device__ __forceinline__ void fill_stage(uint32_t sbase, int i,
                                           int b, int yt, int d) {
    const int s = i & 1;
    const uint32_t mbar = sbase + s * 8;
    const int c0 = i * 4;
    asm volatile("mbarrier.arrive.expect_tx.shared.b64 _, [%0], %1;"
                 :: "r"(mbar), "r"((uint32_t)STAGE_TX) : "memory");
    const char* srcA = (const char*)g_Apad +
        (((long)b * 20 + yt) * NC + c0) * (long)(8 * APAD_W * 4);
    bulk_cp(sbase + A_OFF + s * A_STAGE, srcA, A_STAGE, mbar);
    #pragma unroll
    for (int cc = 0; cc < 4; ++cc) {
        const char* srcB = (const char*)g_Bpad +
            (((long)b * NC + c0 + cc) * BPAD_H + yt * 8 + 20 + d) * (long)(BPAD_W * 4);
        bulk_cp(sbase + B_OFF + s * B_STAGE + cc * B_CC, srcB, B_CC, mbar);
    }
}

// ---------------- Pass 1: raw correlation ----------------
// grid (dyi*2+half, yt, b); block 160 = 8 rows (r) x 20 x-groups (g, 8 x each); 11 dx.
extern __shared__ char smem_dyn[];

__global__ __launch_bounds__(160, 2)
void corr_pass1() {
    const int bx  = blockIdx.x;
    const int dyi = bx >> 1;
    const int d0  = (bx & 1) * 10;
    const int yt  = blockIdx.y;
    const int b   = blockIdx.z;
    const int d   = 2 * dyi - 20;

    const int tid = threadIdx.x;
    const int r   = tid & 7;
    const int g   = tid >> 3;
    const int x0  = g * 8;
    const int y   = yt * 8 + r;

    char* smc = smem_dyn;
    const uint32_t sbase = (uint32_t)__cvta_generic_to_shared(smc);

    if (tid == 0) {
        asm volatile("mbarrier.init.shared.b64 [%0], 1;" :: "r"(sbase + 0) : "memory");
        asm volatile("mbarrier.init.shared.b64 [%0], 1;" :: "r"(sbase + 8) : "memory");
        asm volatile("fence.proxy.async.shared::cta;" ::: "memory");
    }
    __syncthreads();

    if (tid == 0) {
        fill_stage(sbase, 0, b, yt, d);
        fill_stage(sbase, 1, b, yt, d);
    }

    float acc[11][8];
    #pragma unroll
    for (int j = 0; j < 11; ++j)
        #pragma unroll
        for (int o = 0; o < 8; ++o) acc[j][o] = 0.f;

    const int bcol = (d0 >> 1) * 16;   // byte offset of dx-half window inside B row

    for (int i = 0; i < 32; ++i) {
        const int s = i & 1;
        mbar_wait(sbase + s * 8, (i >> 1) & 1);

        #pragma unroll
        for (int cc = 0; cc < 4; ++cc) {
            const float4* aq = (const float4*)(smc + A_OFF + s * A_STAGE +
                                               cc * A_CC + r * A_ROW + x0 * 4);
            const float4* bq = (const float4*)(smc + B_OFF + s * B_STAGE +
                                               cc * B_CC + r * B_ROW + bcol + x0 * 4);
            float a[8], bb[28];
            #pragma unroll
            for (int m = 0; m < 2; ++m) {
                float4 t = aq[m];
                a[4*m+0] = t.x; a[4*m+1] = t.y; a[4*m+2] = t.z; a[4*m+3] = t.w;
            }
            #pragma unroll
            for (int m = 0; m < 7; ++m) {
                float4 t = bq[m];
                bb[4*m+0] = t.x; bb[4*m+1] = t.y; bb[4*m+2] = t.z; bb[4*m+3] = t.w;
            }
            #pragma unroll
            for (int j = 0; j < 11; ++j)
                #pragma unroll
                for (int o = 0; o < 8; ++o)
                    acc[j][o] += a[o] * bb[2 * j + o];
        }
        __syncthreads();
        if (tid == 0 && i + 2 < 32)
            fill_stage(sbase, i + 2, b, yt, d);
    }

    if (y < HR) {
        #pragma unroll
        for (int j = 0; j < 11; ++j) {
            int ch = dyi * ND + (d0 + j);
            size_t base = (((size_t)b * ND2 + ch) * HR + y) * WRP + x0;
            *reinterpret_cast<float4*>(&g_raw[base]) =
                make_float4(acc[j][0], acc[j][1], acc[j][2], acc[j][3]);
            *reinterpret_cast<float4*>(&g_raw[base + 4]) =
                make_float4(acc[j][4], acc[j][5], acc[j][6], acc[j][7]);
        }
    }
}

// ---------------- Pass 2: 3x3 box sum / 1152, 4x4 patch per thread ----------------
__global__ void corr_pass2(float* __restrict__ out) {
    const int tid = threadIdx.x;            // 156
    const int qx = tid % 39;
    const int qy = blockIdx.y * 4 + tid / 39;
    const int ch = blockIdx.z;
    if (qy >= 39) return;
    const int i0 = qy * 4, j0 = qx * 4;
    const float inv = 1.0f / 1152.0f;

    const float* rawb = g_raw + (size_t)ch * HR * WRP;
    float w[6][4];
    #pragma unroll
    for (int rr = 0; rr < 6; ++rr) {
        const float4* p = (const float4*)(rawb + (size_t)(i0 + rr) * WRP + j0);
        float4 u = p[0], v = p[1];
        float f0=u.x, f1=u.y, f2=u.z, f3=u.w, f4=v.x, f5=v.y;
        w[rr][0] = f0 + f1 + f2;
        w[rr][1] = f1 + f2 + f3;
        w[rr][2] = f2 + f3 + f4;
        w[rr][3] = f3 + f4 + f5;
    }
    float* ob = out + (size_t)ch * HO * WO + j0;
    #pragma unroll
    for (int i = 0; i < 4; ++i) {
        float4 o;
        o.x = (w[i][0] + w[i+1][0] + w[i+2][0]) * inv;
        o.y = (w[i][1] + w[i+1][1] + w[i+2][1]) * inv;
        o.z = (w[i][2] + w[i+1][2] + w[i+2][2]) * inv;
        o.w = (w[i][3] + w[i+1][3] + w[i+2][3]) * inv;
        *reinterpret_cast<float4*>(ob + (size_t)(i0 + i) * WO) = o;
    }
}

extern "C" void kernel_launch(void* const* d_in, const int* in_sizes, int n_in,
                              void* d_out, int out_size) {
    const float* in1 = (const float*)d_in[0];
    const float* in2 = (const float*)d_in[1];
    float* out = (float*)d_out;

    {
        long nA = (long)NB * 20 * NC * 8 * APAD_W;
        pad_A<<<(unsigned)((nA + 255) / 256), 256>>>(in1);
        long nBp = (long)NB * NC * BPAD_H * BPAD_W;
        pad_B<<<(unsigned)((nBp + 255) / 256), 256>>>(in2);
    }

    cudaFuncSetAttribute(corr_pass1,
                         cudaFuncAttributeMaxDynamicSharedMemorySize, SMEM_BYTES);

    dim3 g1(42, 20, 4), b1(160);
    corr_pass1<<<g1, b1, SMEM_BYTES>>>();

    dim3 g2(1, 10, NB * ND2), b2(156);
    corr_pass2<<<g2, b2>>>(out);
}